// round 13
// baseline (speedup 1.0000x reference)
#include <cuda_runtime.h>
#include <math.h>

#define N_NODES 100000
#define N_EDGES 3200000
#define CAP 96          // max in-degree slots (Poisson(32): P(deg>96) ~ 1e-20)

// Scratch (static device globals; no allocation). Max stride 16 floats.
__device__ __align__(128) float g_bufA[(size_t)N_NODES * 16];
__device__ __align__(128) float g_bufB[(size_t)N_NODES * 16];
__device__ int    g_cursor[N_NODES];
// +1 node padding: register-pipelined prefetch may read past the last bin
__device__ __align__(128) float2 g_edges[(size_t)(N_NODES + 1) * CAP];

// ---------------------------------------------------------------------------
// Layer-1 dense MM: s1[100000,12] = x[100000,512] @ W1[512,12]  (stride 16 out)
// warp-per-row; W staged row-contiguous [k][0..11] so each k costs 3 LDS.128.
// ---------------------------------------------------------------------------
__global__ void mm1_kernel(const float* __restrict__ x,
                           const float* __restrict__ W,
                           float* __restrict__ out) {
    __shared__ __align__(16) float sW[512 * 12];   // 24 KB, row-major [k][j]
    {
        const float4* Wv = reinterpret_cast<const float4*>(W);
        float4* sWv = reinterpret_cast<float4*>(sW);
        for (int i = threadIdx.x; i < 512 * 12 / 4; i += blockDim.x)
            sWv[i] = Wv[i];
    }
    __syncthreads();

    int warp = (blockIdx.x * blockDim.x + threadIdx.x) >> 5;
    int lane = threadIdx.x & 31;
    if (warp >= N_NODES) return;

    const float4* xr = reinterpret_cast<const float4*>(x + (size_t)warp * 512);
    float acc[12];
#pragma unroll
    for (int j = 0; j < 12; j++) acc[j] = 0.f;

#pragma unroll
    for (int it = 0; it < 4; it++) {
        int k4 = it * 32 + lane;     // float4 index
        float4 xv = xr[k4];
        int k = k4 * 4;
        const float4* w0 = reinterpret_cast<const float4*>(sW + (k + 0) * 12);
        const float4* w1 = reinterpret_cast<const float4*>(sW + (k + 1) * 12);
        const float4* w2 = reinterpret_cast<const float4*>(sW + (k + 2) * 12);
        const float4* w3 = reinterpret_cast<const float4*>(sW + (k + 3) * 12);
#pragma unroll
        for (int c = 0; c < 3; c++) {
            float4 a = w0[c], b = w1[c], d = w2[c], e = w3[c];
            acc[4 * c + 0] = fmaf(xv.x, a.x, acc[4 * c + 0]);
            acc[4 * c + 1] = fmaf(xv.x, a.y, acc[4 * c + 1]);
            acc[4 * c + 2] = fmaf(xv.x, a.z, acc[4 * c + 2]);
            acc[4 * c + 3] = fmaf(xv.x, a.w, acc[4 * c + 3]);
            acc[4 * c + 0] = fmaf(xv.y, b.x, acc[4 * c + 0]);
            acc[4 * c + 1] = fmaf(xv.y, b.y, acc[4 * c + 1]);
            acc[4 * c + 2] = fmaf(xv.y, b.z, acc[4 * c + 2]);
            acc[4 * c + 3] = fmaf(xv.y, b.w, acc[4 * c + 3]);
            acc[4 * c + 0] = fmaf(xv.z, d.x, acc[4 * c + 0]);
            acc[4 * c + 1] = fmaf(xv.z, d.y, acc[4 * c + 1]);
            acc[4 * c + 2] = fmaf(xv.z, d.z, acc[4 * c + 2]);
            acc[4 * c + 3] = fmaf(xv.z, d.w, acc[4 * c + 3]);
            acc[4 * c + 0] = fmaf(xv.w, e.x, acc[4 * c + 0]);
            acc[4 * c + 1] = fmaf(xv.w, e.y, acc[4 * c + 1]);
            acc[4 * c + 2] = fmaf(xv.w, e.z, acc[4 * c + 2]);
            acc[4 * c + 3] = fmaf(xv.w, e.w, acc[4 * c + 3]);
        }
    }
#pragma unroll
    for (int j = 0; j < 12; j++) {
#pragma unroll
        for (int o = 16; o > 0; o >>= 1)
            acc[j] += __shfl_down_sync(0xffffffffu, acc[j], o);
    }
    if (lane == 0) {
        float* o = out + (size_t)warp * 16;
#pragma unroll
        for (int j = 0; j < 12; j++) o[j] = acc[j];
    }
}

// ---------------------------------------------------------------------------
// Bin edges by destination, 4 edges per thread (vector index loads).
// ---------------------------------------------------------------------------
__global__ void fill_bins_kernel(const float* __restrict__ ev,
                                 const int* __restrict__ src,
                                 const int* __restrict__ dst) {
    int t = blockIdx.x * blockDim.x + threadIdx.x;
    int e = t * 4;
    if (e + 4 <= N_EDGES) {
        float4 v4 = *reinterpret_cast<const float4*>(ev + e);
        int4 s4 = *reinterpret_cast<const int4*>(src + e);
        int4 d4 = *reinterpret_cast<const int4*>(dst + e);
        int p0 = atomicAdd(&g_cursor[d4.x], 1);
        int p1 = atomicAdd(&g_cursor[d4.y], 1);
        int p2 = atomicAdd(&g_cursor[d4.z], 1);
        int p3 = atomicAdd(&g_cursor[d4.w], 1);
        if (p0 < CAP) g_edges[(size_t)d4.x * CAP + p0] = make_float2(v4.x, __int_as_float(s4.x));
        if (p1 < CAP) g_edges[(size_t)d4.y * CAP + p1] = make_float2(v4.y, __int_as_float(s4.y));
        if (p2 < CAP) g_edges[(size_t)d4.z * CAP + p2] = make_float2(v4.z, __int_as_float(s4.z));
        if (p3 < CAP) g_edges[(size_t)d4.w * CAP + p3] = make_float2(v4.w, __int_as_float(s4.w));
    } else {
        for (; e < N_EDGES; e++) {
            int d = dst[e];
            int pos = atomicAdd(&g_cursor[d], 1);
            if (pos < CAP)
                g_edges[(size_t)d * CAP + pos] = make_float2(ev[e], __int_as_float(src[e]));
        }
    }
}

// ---------------------------------------------------------------------------
// STAGED gather (wide layers, SUB=16/NPW=2): edge list staged into smem with
// cached loads (L2-persistent across passes), then 8 row-LDGs in flight/lane.
// ---------------------------------------------------------------------------
template <int DIN, int SUB, int SIN, int DOUT, int SOUT,
          int ACT, bool BPRE, bool GEMM, bool BPOST>
__global__ void __launch_bounds__(256, 8)
gather_staged_kernel(const float* __restrict__ s,
                     const float* __restrict__ W,
                     const float* __restrict__ bpre,
                     const float* __restrict__ bpost,
                     float* __restrict__ out) {
    constexpr int NPW = 32 / SUB;     // nodes per warp
    constexpr int N4 = CAP / 2;       // float4 slots per node (48)
    __shared__ float4 sel[8][NPW][N4 + 1];
    __shared__ float sW[GEMM ? DIN * DOUT : 1];
    __shared__ float sbpre[DIN];
    __shared__ float sbpost[BPOST ? DOUT : 1];
    __shared__ float sh[8][NPW][SUB];

    if (GEMM)
        for (int i = threadIdx.x; i < DIN * DOUT; i += blockDim.x) sW[i] = W[i];
    if (BPRE && threadIdx.x < DIN) sbpre[threadIdx.x] = bpre[threadIdx.x];
    if (BPOST && threadIdx.x < DOUT) sbpost[threadIdx.x] = bpost[threadIdx.x];
    __syncthreads();

    const int warpid = threadIdx.x >> 5;
    const int lane = threadIdx.x & 31;
    const int sub = lane / SUB;
    const int j = lane & (SUB - 1);
    const int node = ((blockIdx.x * blockDim.x + threadIdx.x) >> 5) * NPW + sub;
    const bool valid = node < N_NODES;

    int deg = 0;
    if (valid) {
        deg = g_cursor[node];
        deg = deg < CAP ? deg : CAP;
    }

    // stage packed edge list into smem (cached loads -> L2-resident for later passes)
    {
        const float4* el4 = reinterpret_cast<const float4*>(&g_edges[(size_t)node * CAP]);
        int n4 = (deg + 1) >> 1;
        for (int c = j; c < n4; c += SUB)
            sel[warpid][sub][c] = __ldg(el4 + c);
    }
    __syncwarp();

    const unsigned joff = (j < DIN) ? (unsigned)j : 0u;
    const float* scol = s + joff;
    const float4* myel = sel[warpid][sub];

    float a0 = 0.f, a1 = 0.f, a2 = 0.f, a3 = 0.f;
    const int iters = deg >> 3;

    for (int it = 0; it < iters; it++) {
        float4 p0 = myel[4 * it + 0];
        float4 p1 = myel[4 * it + 1];
        float4 p2 = myel[4 * it + 2];
        float4 p3 = myel[4 * it + 3];
        float r0 = __ldg(scol + (unsigned)__float_as_int(p0.y) * SIN);
        float r1 = __ldg(scol + (unsigned)__float_as_int(p0.w) * SIN);
        float r2 = __ldg(scol + (unsigned)__float_as_int(p1.y) * SIN);
        float r3 = __ldg(scol + (unsigned)__float_as_int(p1.w) * SIN);
        float r4 = __ldg(scol + (unsigned)__float_as_int(p2.y) * SIN);
        float r5 = __ldg(scol + (unsigned)__float_as_int(p2.w) * SIN);
        float r6 = __ldg(scol + (unsigned)__float_as_int(p3.y) * SIN);
        float r7 = __ldg(scol + (unsigned)__float_as_int(p3.w) * SIN);
        a0 = fmaf(p0.x, r0, a0);
        a1 = fmaf(p0.z, r1, a1);
        a2 = fmaf(p1.x, r2, a2);
        a3 = fmaf(p1.z, r3, a3);
        a0 = fmaf(p2.x, r4, a0);
        a1 = fmaf(p2.z, r5, a1);
        a2 = fmaf(p3.x, r6, a2);
        a3 = fmaf(p3.z, r7, a3);
    }
    {
        const float2* selt = reinterpret_cast<const float2*>(myel);
        for (int e = iters << 3; e < deg; e++) {
            float2 ed = selt[e];
            a0 = fmaf(ed.x, __ldg(scol + (unsigned)__float_as_int(ed.y) * SIN), a0);
        }
    }
    float acc = (a0 + a1) + (a2 + a3);

    float h = acc;
    if (j < DIN) {
        if (BPRE) h += sbpre[j];
        if (ACT == 1) h = fmaxf(h, 0.f);
        else if (ACT == 2) h = h - tanhf(h);
    } else {
        h = 0.f;
    }

    if (!GEMM) {
        if (valid && j < DIN) out[(size_t)node * SOUT + j] = h;
        return;
    }

    sh[warpid][sub][j] = h;
    __syncwarp();

    if (valid) {
#pragma unroll
        for (int jo = j; jo < DOUT; jo += SUB) {
            float a = BPOST ? sbpost[jo] : 0.f;
#pragma unroll
            for (int k = 0; k < DIN; k++)
                a = fmaf(sh[warpid][sub][k], sW[k * DOUT + jo], a);
            out[(size_t)node * SOUT + jo] = a;
        }
    }
}

// ---------------------------------------------------------------------------
// REGISTER-PIPELINED gather (narrow layers): unroll-4 with elist prefetch.
// Cached elist loads for L2 persistence.
// ---------------------------------------------------------------------------
template <int DIN, int SUB, int SIN, int DOUT, int SOUT,
          int ACT, bool BPRE, bool GEMM, bool BPOST>
__global__ void __launch_bounds__(256, 6)
gather_reg_kernel(const float* __restrict__ s,
                  const float* __restrict__ W,
                  const float* __restrict__ bpre,
                  const float* __restrict__ bpost,
                  float* __restrict__ out) {
    constexpr int NPW = 32 / SUB;
    __shared__ float sW[GEMM ? DIN * DOUT : 1];
    __shared__ float sbpre[DIN];
    __shared__ float sbpost[BPOST ? DOUT : 1];
    __shared__ float sh[8][NPW][SUB];

    if (GEMM)
        for (int i = threadIdx.x; i < DIN * DOUT; i += blockDim.x) sW[i] = W[i];
    if (BPRE && threadIdx.x < DIN) sbpre[threadIdx.x] = bpre[threadIdx.x];
    if (BPOST && threadIdx.x < DOUT) sbpost[threadIdx.x] = bpost[threadIdx.x];
    __syncthreads();

    const int warpid = threadIdx.x >> 5;
    const int lane = threadIdx.x & 31;
    const int sub = lane / SUB;
    const int j = lane & (SUB - 1);
    const int node = ((blockIdx.x * blockDim.x + threadIdx.x) >> 5) * NPW + sub;
    const bool valid = node < N_NODES;

    int deg = 0;
    if (valid) {
        deg = g_cursor[node];
        deg = deg < CAP ? deg : CAP;
    }

    const float4* el4 = reinterpret_cast<const float4*>(&g_edges[(size_t)node * CAP]);
    const unsigned joff = (j < DIN) ? (unsigned)j : 0u;
    const float* scol = s + joff;

    float a0 = 0.f, a1 = 0.f, a2 = 0.f, a3 = 0.f;
    const int iters = deg >> 2;

    float4 q0, q1;
    if (iters > 0) { q0 = __ldg(el4 + 0); q1 = __ldg(el4 + 1); }
    for (int it = 0; it < iters; it++) {
        float4 p0 = q0, p1 = q1;
        q0 = __ldg(el4 + 2 * it + 2);
        q1 = __ldg(el4 + 2 * it + 3);
        float r0 = __ldg(scol + (unsigned)__float_as_int(p0.y) * SIN);
        float r1 = __ldg(scol + (unsigned)__float_as_int(p0.w) * SIN);
        float r2 = __ldg(scol + (unsigned)__float_as_int(p1.y) * SIN);
        float r3 = __ldg(scol + (unsigned)__float_as_int(p1.w) * SIN);
        a0 = fmaf(p0.x, r0, a0);
        a1 = fmaf(p0.z, r1, a1);
        a2 = fmaf(p1.x, r2, a2);
        a3 = fmaf(p1.z, r3, a3);
    }
    for (int e = iters << 2; e < deg; e++) {
        float2 ed = g_edges[(size_t)node * CAP + e];
        a0 = fmaf(ed.x, __ldg(scol + (unsigned)__float_as_int(ed.y) * SIN), a0);
    }
    float acc = (a0 + a1) + (a2 + a3);

    float h = acc;
    if (j < DIN) {
        if (BPRE) h += sbpre[j];
        if (ACT == 1) h = fmaxf(h, 0.f);
        else if (ACT == 2) h = h - tanhf(h);
    } else {
        h = 0.f;
    }

    if (!GEMM) {
        if (valid && j < DIN) out[(size_t)node * SOUT + j] = h;
        return;
    }

    sh[warpid][sub][j] = h;
    __syncwarp();

    if (valid) {
#pragma unroll
        for (int jo = j; jo < DOUT; jo += SUB) {
            float a = BPOST ? sbpost[jo] : 0.f;
#pragma unroll
            for (int k = 0; k < DIN; k++)
                a = fmaf(sh[warpid][sub][k], sW[k * DOUT + jo], a);
            out[(size_t)node * SOUT + jo] = a;
        }
    }
}

// ---------------------------------------------------------------------------
// Launch
// ---------------------------------------------------------------------------
extern "C" void kernel_launch(void* const* d_in, const int* in_sizes, int n_in,
                              void* d_out, int out_size) {
    const float* x = nullptr;
    const float* ev = nullptr;
    const int* esrc = nullptr;
    const int* edst = nullptr;
    const float* W[6] = {0};
    const float* b[6] = {0};
    const int wsz[6] = {512 * 12, 12 * 10, 10 * 8, 8 * 6, 6 * 4, 4 * 7};
    const int bsz[6] = {12, 10, 8, 6, 4, 7};

    int edgeSeen = 0;
    for (int i = 0; i < n_in; i++) {
        int sz = in_sizes[i];
        if (sz == N_NODES * 512) {
            x = (const float*)d_in[i];
        } else if (sz == N_EDGES) {
            if (edgeSeen == 0) ev = (const float*)d_in[i];
            else if (edgeSeen == 1) esrc = (const int*)d_in[i];
            else edst = (const int*)d_in[i];
            edgeSeen++;
        } else {
            for (int j = 0; j < 6; j++) {
                if (sz == wsz[j]) W[j] = (const float*)d_in[i];
                else if (sz == bsz[j]) b[j] = (const float*)d_in[i];
            }
        }
    }

    float* bufA = nullptr;
    float* bufB = nullptr;
    int* cursor = nullptr;
    cudaGetSymbolAddress((void**)&bufA, g_bufA);
    cudaGetSymbolAddress((void**)&bufB, g_bufB);
    cudaGetSymbolAddress((void**)&cursor, g_cursor);
    float* out = (float*)d_out;

    const int TB = 256;
    auto blocks = [](long long n, int tb) { return (int)((n + tb - 1) / tb); };

    const int WB = blocks((long long)N_NODES * 32, TB);
    auto gridFor = [&](int NPW) {
        long long warps = (N_NODES + NPW - 1) / NPW;
        return blocks(warps * 32, TB);
    };

    // Build dst bins (once per launch)
    cudaMemsetAsync(cursor, 0, (size_t)N_NODES * sizeof(int));
    fill_bins_kernel<<<blocks((N_EDGES + 3) / 4, TB), TB>>>(ev, esrc, edst);

    // s1 = x @ W1  (12 wide, stride 16) -> bufA
    mm1_kernel<<<WB, TB>>>(x, W[0], bufA);

    // p1: h1 = agg(s1)+b1 ; s2 = h1@W2         (DIN=12 SUB=16 SIN=16 -> 10w s16)
    gather_staged_kernel<12, 16, 16, 10, 16, 0, true, true, false>
        <<<gridFor(2), TB>>>(bufA, W[1], b[0], nullptr, bufB);
    // p2: h2 = relu(agg(s2)+b2) ; s3 = h2@W3   (DIN=10 SUB=16 SIN=16 -> 8w s8)
    gather_staged_kernel<10, 16, 16, 8, 8, 1, true, true, false>
        <<<gridFor(2), TB>>>(bufB, W[2], b[1], nullptr, bufA);
    // p3: h3 = ts(agg(s3)+b3) ; s4 = h3@W4     (DIN=8 SUB=8 SIN=8 -> 6w s8)
    gather_reg_kernel<8, 8, 8, 6, 8, 2, true, true, false>
        <<<gridFor(4), TB>>>(bufA, W[3], b[2], nullptr, bufB);
    // p4: h4 = ts(agg(s4)+b4) ; s5 = h4@W5     (DIN=6 SUB=8 SIN=8 -> 4w s4)
    gather_reg_kernel<6, 8, 8, 4, 4, 2, true, true, false>
        <<<gridFor(4), TB>>>(bufB, W[4], b[3], nullptr, bufA);
    // p5: h5 = agg(s5)+b5                      (DIN=4 SUB=4 SIN=4 -> 4w s4, no GEMM)
    gather_reg_kernel<4, 4, 4, 4, 4, 0, true, false, false>
        <<<gridFor(8), TB>>>(bufA, nullptr, b[4], nullptr, bufB);
    // p6: out = (agg(h5))@W6 + b6              (DIN=4 SUB=4 SIN=4 -> 7w packed)
    gather_reg_kernel<4, 4, 4, 7, 7, 0, false, true, true>
        <<<gridFor(8), TB>>>(bufB, W[5], nullptr, b[5], out);

    (void)out_size;
}

// round 14
// speedup vs baseline: 1.5337x; 1.5337x over previous
#include <cuda_runtime.h>
#include <math.h>

#define N_NODES 100000
#define N_EDGES 3200000
#define CAP 96          // max in-degree slots (Poisson(32): P(deg>96) ~ 1e-20)

// Scratch (static device globals; no allocation). Max stride 16 floats.
__device__ __align__(128) float g_bufA[(size_t)N_NODES * 16];
__device__ __align__(128) float g_bufB[(size_t)N_NODES * 16];
__device__ int    g_cursor[N_NODES];
// +1 node padding: register-pipelined prefetch may read past the last bin
__device__ __align__(128) float2 g_edges[(size_t)(N_NODES + 1) * CAP];

// ---------------------------------------------------------------------------
// Layer-1 dense MM: s1[100000,12] = x[100000,512] @ W1[512,12]  (stride 16 out)
// warp-per-row, float4 x loads, W1 staged in shared (pad 13 -> 4-way max).
// [R11 version verbatim — proven in the 334us run]
// ---------------------------------------------------------------------------
__global__ void mm1_kernel(const float* __restrict__ x,
                           const float* __restrict__ W,
                           float* __restrict__ out) {
    __shared__ float sW[512 * 13];
    for (int i = threadIdx.x; i < 512 * 12; i += blockDim.x) {
        int k = i / 12, j = i % 12;
        sW[k * 13 + j] = W[i];
    }
    __syncthreads();

    int warp = (blockIdx.x * blockDim.x + threadIdx.x) >> 5;
    int lane = threadIdx.x & 31;
    if (warp >= N_NODES) return;

    const float4* xr = reinterpret_cast<const float4*>(x + (size_t)warp * 512);
    float acc[12];
#pragma unroll
    for (int j = 0; j < 12; j++) acc[j] = 0.f;

#pragma unroll
    for (int it = 0; it < 4; it++) {
        int k4 = it * 32 + lane;
        float4 xv = xr[k4];
        int k = k4 * 4;
#pragma unroll
        for (int j = 0; j < 12; j++) {
            acc[j] = fmaf(xv.x, sW[(k + 0) * 13 + j], acc[j]);
            acc[j] = fmaf(xv.y, sW[(k + 1) * 13 + j], acc[j]);
            acc[j] = fmaf(xv.z, sW[(k + 2) * 13 + j], acc[j]);
            acc[j] = fmaf(xv.w, sW[(k + 3) * 13 + j], acc[j]);
        }
    }
#pragma unroll
    for (int j = 0; j < 12; j++) {
#pragma unroll
        for (int o = 16; o > 0; o >>= 1)
            acc[j] += __shfl_down_sync(0xffffffffu, acc[j], o);
    }
    if (lane == 0) {
        float* o = out + (size_t)warp * 16;
#pragma unroll
        for (int j = 0; j < 12; j++) o[j] = acc[j];
    }
}

// ---------------------------------------------------------------------------
// Bin edges by destination, 4 edges per thread (vector index loads).
// ---------------------------------------------------------------------------
__global__ void fill_bins_kernel(const float* __restrict__ ev,
                                 const int* __restrict__ src,
                                 const int* __restrict__ dst) {
    int t = blockIdx.x * blockDim.x + threadIdx.x;
    int e = t * 4;
    if (e + 4 <= N_EDGES) {
        float4 v4 = *reinterpret_cast<const float4*>(ev + e);
        int4 s4 = *reinterpret_cast<const int4*>(src + e);
        int4 d4 = *reinterpret_cast<const int4*>(dst + e);
        int p0 = atomicAdd(&g_cursor[d4.x], 1);
        int p1 = atomicAdd(&g_cursor[d4.y], 1);
        int p2 = atomicAdd(&g_cursor[d4.z], 1);
        int p3 = atomicAdd(&g_cursor[d4.w], 1);
        if (p0 < CAP) g_edges[(size_t)d4.x * CAP + p0] = make_float2(v4.x, __int_as_float(s4.x));
        if (p1 < CAP) g_edges[(size_t)d4.y * CAP + p1] = make_float2(v4.y, __int_as_float(s4.y));
        if (p2 < CAP) g_edges[(size_t)d4.z * CAP + p2] = make_float2(v4.z, __int_as_float(s4.z));
        if (p3 < CAP) g_edges[(size_t)d4.w * CAP + p3] = make_float2(v4.w, __int_as_float(s4.w));
    } else {
        for (; e < N_EDGES; e++) {
            int d = dst[e];
            int pos = atomicAdd(&g_cursor[d], 1);
            if (pos < CAP)
                g_edges[(size_t)d * CAP + pos] = make_float2(ev[e], __int_as_float(src[e]));
        }
    }
}

// ---------------------------------------------------------------------------
// STAGED gather (wide layers, SUB=16/NPW=2): edge list staged into smem with
// cached loads (L2-persistent across passes), then 8 row-LDGs in flight/lane.
// ---------------------------------------------------------------------------
template <int DIN, int SUB, int SIN, int DOUT, int SOUT,
          int ACT, bool BPRE, bool GEMM, bool BPOST>
__global__ void __launch_bounds__(256, 8)
gather_staged_kernel(const float* __restrict__ s,
                     const float* __restrict__ W,
                     const float* __restrict__ bpre,
                     const float* __restrict__ bpost,
                     float* __restrict__ out) {
    constexpr int NPW = 32 / SUB;     // nodes per warp
    constexpr int N4 = CAP / 2;       // float4 slots per node (48)
    __shared__ float4 sel[8][NPW][N4 + 1];
    __shared__ float sW[GEMM ? DIN * DOUT : 1];
    __shared__ float sbpre[DIN];
    __shared__ float sbpost[BPOST ? DOUT : 1];
    __shared__ float sh[8][NPW][SUB];

    if (GEMM)
        for (int i = threadIdx.x; i < DIN * DOUT; i += blockDim.x) sW[i] = W[i];
    if (BPRE && threadIdx.x < DIN) sbpre[threadIdx.x] = bpre[threadIdx.x];
    if (BPOST && threadIdx.x < DOUT) sbpost[threadIdx.x] = bpost[threadIdx.x];
    __syncthreads();

    const int warpid = threadIdx.x >> 5;
    const int lane = threadIdx.x & 31;
    const int sub = lane / SUB;
    const int j = lane & (SUB - 1);
    const int node = ((blockIdx.x * blockDim.x + threadIdx.x) >> 5) * NPW + sub;
    const bool valid = node < N_NODES;

    int deg = 0;
    if (valid) {
        deg = g_cursor[node];
        deg = deg < CAP ? deg : CAP;
    }

    // stage packed edge list into smem (cached loads -> L2-resident for later passes)
    {
        const float4* el4 = reinterpret_cast<const float4*>(&g_edges[(size_t)node * CAP]);
        int n4 = (deg + 1) >> 1;
        for (int c = j; c < n4; c += SUB)
            sel[warpid][sub][c] = __ldg(el4 + c);
    }
    __syncwarp();

    const unsigned joff = (j < DIN) ? (unsigned)j : 0u;
    const float* scol = s + joff;
    const float4* myel = sel[warpid][sub];

    float a0 = 0.f, a1 = 0.f, a2 = 0.f, a3 = 0.f;
    const int iters = deg >> 3;

    for (int it = 0; it < iters; it++) {
        float4 p0 = myel[4 * it + 0];
        float4 p1 = myel[4 * it + 1];
        float4 p2 = myel[4 * it + 2];
        float4 p3 = myel[4 * it + 3];
        float r0 = __ldg(scol + (unsigned)__float_as_int(p0.y) * SIN);
        float r1 = __ldg(scol + (unsigned)__float_as_int(p0.w) * SIN);
        float r2 = __ldg(scol + (unsigned)__float_as_int(p1.y) * SIN);
        float r3 = __ldg(scol + (unsigned)__float_as_int(p1.w) * SIN);
        float r4 = __ldg(scol + (unsigned)__float_as_int(p2.y) * SIN);
        float r5 = __ldg(scol + (unsigned)__float_as_int(p2.w) * SIN);
        float r6 = __ldg(scol + (unsigned)__float_as_int(p3.y) * SIN);
        float r7 = __ldg(scol + (unsigned)__float_as_int(p3.w) * SIN);
        a0 = fmaf(p0.x, r0, a0);
        a1 = fmaf(p0.z, r1, a1);
        a2 = fmaf(p1.x, r2, a2);
        a3 = fmaf(p1.z, r3, a3);
        a0 = fmaf(p2.x, r4, a0);
        a1 = fmaf(p2.z, r5, a1);
        a2 = fmaf(p3.x, r6, a2);
        a3 = fmaf(p3.z, r7, a3);
    }
    {
        const float2* selt = reinterpret_cast<const float2*>(myel);
        for (int e = iters << 3; e < deg; e++) {
            float2 ed = selt[e];
            a0 = fmaf(ed.x, __ldg(scol + (unsigned)__float_as_int(ed.y) * SIN), a0);
        }
    }
    float acc = (a0 + a1) + (a2 + a3);

    float h = acc;
    if (j < DIN) {
        if (BPRE) h += sbpre[j];
        if (ACT == 1) h = fmaxf(h, 0.f);
        else if (ACT == 2) h = h - tanhf(h);
    } else {
        h = 0.f;
    }

    if (!GEMM) {
        if (valid && j < DIN) out[(size_t)node * SOUT + j] = h;
        return;
    }

    sh[warpid][sub][j] = h;
    __syncwarp();

    if (valid) {
#pragma unroll
        for (int jo = j; jo < DOUT; jo += SUB) {
            float a = BPOST ? sbpost[jo] : 0.f;
#pragma unroll
            for (int k = 0; k < DIN; k++)
                a = fmaf(sh[warpid][sub][k], sW[k * DOUT + jo], a);
            out[(size_t)node * SOUT + jo] = a;
        }
    }
}

// ---------------------------------------------------------------------------
// REGISTER-PIPELINED gather (narrow layers): unroll-4 with elist prefetch.
// Cached elist loads for L2 persistence.
// ---------------------------------------------------------------------------
template <int DIN, int SUB, int SIN, int DOUT, int SOUT,
          int ACT, bool BPRE, bool GEMM, bool BPOST>
__global__ void __launch_bounds__(256, 6)
gather_reg_kernel(const float* __restrict__ s,
                  const float* __restrict__ W,
                  const float* __restrict__ bpre,
                  const float* __restrict__ bpost,
                  float* __restrict__ out) {
    constexpr int NPW = 32 / SUB;
    __shared__ float sW[GEMM ? DIN * DOUT : 1];
    __shared__ float sbpre[DIN];
    __shared__ float sbpost[BPOST ? DOUT : 1];
    __shared__ float sh[8][NPW][SUB];

    if (GEMM)
        for (int i = threadIdx.x; i < DIN * DOUT; i += blockDim.x) sW[i] = W[i];
    if (BPRE && threadIdx.x < DIN) sbpre[threadIdx.x] = bpre[threadIdx.x];
    if (BPOST && threadIdx.x < DOUT) sbpost[threadIdx.x] = bpost[threadIdx.x];
    __syncthreads();

    const int warpid = threadIdx.x >> 5;
    const int lane = threadIdx.x & 31;
    const int sub = lane / SUB;
    const int j = lane & (SUB - 1);
    const int node = ((blockIdx.x * blockDim.x + threadIdx.x) >> 5) * NPW + sub;
    const bool valid = node < N_NODES;

    int deg = 0;
    if (valid) {
        deg = g_cursor[node];
        deg = deg < CAP ? deg : CAP;
    }

    const float4* el4 = reinterpret_cast<const float4*>(&g_edges[(size_t)node * CAP]);
    const unsigned joff = (j < DIN) ? (unsigned)j : 0u;
    const float* scol = s + joff;

    float a0 = 0.f, a1 = 0.f, a2 = 0.f, a3 = 0.f;
    const int iters = deg >> 2;

    float4 q0, q1;
    if (iters > 0) { q0 = __ldg(el4 + 0); q1 = __ldg(el4 + 1); }
    for (int it = 0; it < iters; it++) {
        float4 p0 = q0, p1 = q1;
        q0 = __ldg(el4 + 2 * it + 2);
        q1 = __ldg(el4 + 2 * it + 3);
        float r0 = __ldg(scol + (unsigned)__float_as_int(p0.y) * SIN);
        float r1 = __ldg(scol + (unsigned)__float_as_int(p0.w) * SIN);
        float r2 = __ldg(scol + (unsigned)__float_as_int(p1.y) * SIN);
        float r3 = __ldg(scol + (unsigned)__float_as_int(p1.w) * SIN);
        a0 = fmaf(p0.x, r0, a0);
        a1 = fmaf(p0.z, r1, a1);
        a2 = fmaf(p1.x, r2, a2);
        a3 = fmaf(p1.z, r3, a3);
    }
    for (int e = iters << 2; e < deg; e++) {
        float2 ed = g_edges[(size_t)node * CAP + e];
        a0 = fmaf(ed.x, __ldg(scol + (unsigned)__float_as_int(ed.y) * SIN), a0);
    }
    float acc = (a0 + a1) + (a2 + a3);

    float h = acc;
    if (j < DIN) {
        if (BPRE) h += sbpre[j];
        if (ACT == 1) h = fmaxf(h, 0.f);
        else if (ACT == 2) h = h - tanhf(h);
    } else {
        h = 0.f;
    }

    if (!GEMM) {
        if (valid && j < DIN) out[(size_t)node * SOUT + j] = h;
        return;
    }

    sh[warpid][sub][j] = h;
    __syncwarp();

    if (valid) {
#pragma unroll
        for (int jo = j; jo < DOUT; jo += SUB) {
            float a = BPOST ? sbpost[jo] : 0.f;
#pragma unroll
            for (int k = 0; k < DIN; k++)
                a = fmaf(sh[warpid][sub][k], sW[k * DOUT + jo], a);
            out[(size_t)node * SOUT + jo] = a;
        }
    }
}

// ---------------------------------------------------------------------------
// Launch. fill_bins runs on a side stream, fork-join overlapped with mm1.
// ---------------------------------------------------------------------------
extern "C" void kernel_launch(void* const* d_in, const int* in_sizes, int n_in,
                              void* d_out, int out_size) {
    const float* x = nullptr;
    const float* ev = nullptr;
    const int* esrc = nullptr;
    const int* edst = nullptr;
    const float* W[6] = {0};
    const float* b[6] = {0};
    const int wsz[6] = {512 * 12, 12 * 10, 10 * 8, 8 * 6, 6 * 4, 4 * 7};
    const int bsz[6] = {12, 10, 8, 6, 4, 7};

    int edgeSeen = 0;
    for (int i = 0; i < n_in; i++) {
        int sz = in_sizes[i];
        if (sz == N_NODES * 512) {
            x = (const float*)d_in[i];
        } else if (sz == N_EDGES) {
            if (edgeSeen == 0) ev = (const float*)d_in[i];
            else if (edgeSeen == 1) esrc = (const int*)d_in[i];
            else edst = (const int*)d_in[i];
            edgeSeen++;
        } else {
            for (int j = 0; j < 6; j++) {
                if (sz == wsz[j]) W[j] = (const float*)d_in[i];
                else if (sz == bsz[j]) b[j] = (const float*)d_in[i];
            }
        }
    }

    float* bufA = nullptr;
    float* bufB = nullptr;
    int* cursor = nullptr;
    cudaGetSymbolAddress((void**)&bufA, g_bufA);
    cudaGetSymbolAddress((void**)&bufB, g_bufB);
    cudaGetSymbolAddress((void**)&cursor, g_cursor);
    float* out = (float*)d_out;

    const int TB = 256;
    auto blocks = [](long long n, int tb) { return (int)((n + tb - 1) / tb); };

    const int WB = blocks((long long)N_NODES * 32, TB);
    auto gridFor = [&](int NPW) {
        long long warps = (N_NODES + NPW - 1) / NPW;
        return blocks(warps * 32, TB);
    };

    // ---- fork: fill_bins (side stream) || mm1 (main stream) ----
    cudaStream_t side = 0;
    cudaEvent_t evFork = 0, evJoin = 0;
    bool forked = (cudaStreamCreateWithFlags(&side, cudaStreamNonBlocking) == cudaSuccess) &&
                  (cudaEventCreateWithFlags(&evFork, cudaEventDisableTiming) == cudaSuccess) &&
                  (cudaEventCreateWithFlags(&evJoin, cudaEventDisableTiming) == cudaSuccess);

    cudaMemsetAsync(cursor, 0, (size_t)N_NODES * sizeof(int));
    if (forked) {
        cudaEventRecord(evFork, cudaStreamPerThread);      // after memset
        cudaStreamWaitEvent(side, evFork, 0);
        fill_bins_kernel<<<blocks((N_EDGES + 3) / 4, TB), TB, 0, side>>>(ev, esrc, edst);
        mm1_kernel<<<WB, TB>>>(x, W[0], bufA);             // main stream, concurrent
        cudaEventRecord(evJoin, side);
        cudaStreamWaitEvent(cudaStreamPerThread, evJoin, 0);
    } else {
        fill_bins_kernel<<<blocks((N_EDGES + 3) / 4, TB), TB>>>(ev, esrc, edst);
        mm1_kernel<<<WB, TB>>>(x, W[0], bufA);
    }

    // p1: h1 = agg(s1)+b1 ; s2 = h1@W2         (DIN=12 SUB=16 SIN=16 -> 10w s16)
    gather_staged_kernel<12, 16, 16, 10, 16, 0, true, true, false>
        <<<gridFor(2), TB>>>(bufA, W[1], b[0], nullptr, bufB);
    // p2: h2 = relu(agg(s2)+b2) ; s3 = h2@W3   (DIN=10 SUB=16 SIN=16 -> 8w s8)
    gather_staged_kernel<10, 16, 16, 8, 8, 1, true, true, false>
        <<<gridFor(2), TB>>>(bufB, W[2], b[1], nullptr, bufA);
    // p3: h3 = ts(agg(s3)+b3) ; s4 = h3@W4     (DIN=8 SUB=8 SIN=8 -> 6w s8)
    gather_reg_kernel<8, 8, 8, 6, 8, 2, true, true, false>
        <<<gridFor(4), TB>>>(bufA, W[3], b[2], nullptr, bufB);
    // p4: h4 = ts(agg(s4)+b4) ; s5 = h4@W5     (DIN=6 SUB=8 SIN=8 -> 4w s4)
    gather_reg_kernel<6, 8, 8, 4, 4, 2, true, true, false>
        <<<gridFor(4), TB>>>(bufB, W[4], b[3], nullptr, bufA);
    // p5: h5 = agg(s5)+b5                      (DIN=4 SUB=4 SIN=4 -> 4w s4, no GEMM)
    gather_reg_kernel<4, 4, 4, 4, 4, 0, true, false, false>
        <<<gridFor(8), TB>>>(bufA, nullptr, b[4], nullptr, bufB);
    // p6: out = (agg(h5))@W6 + b6              (DIN=4 SUB=4 SIN=4 -> 7w packed)
    gather_reg_kernel<4, 4, 4, 7, 7, 0, false, true, true>
        <<<gridFor(8), TB>>>(bufB, W[5], nullptr, b[5], out);

    if (forked) {
        cudaStreamDestroy(side);
        cudaEventDestroy(evFork);
        cudaEventDestroy(evJoin);
    }

    (void)out_size;
}

// round 15
// speedup vs baseline: 1.5433x; 1.0062x over previous
#include <cuda_runtime.h>
#include <cuda_fp16.h>
#include <math.h>

#define N_NODES 100000
#define N_EDGES 3200000
#define CAP 96          // max in-degree slots (Poisson(32): P(deg>96) ~ 1e-20)

// Scratch (static device globals; no allocation). Max stride 16 floats.
__device__ __align__(128) float g_bufA[(size_t)N_NODES * 16];
__device__ __align__(128) float g_bufB[(size_t)N_NODES * 16];
__device__ int    g_cursor[N_NODES];
// +1 node padding: register-pipelined prefetch may read past the last bin
__device__ __align__(128) float2 g_edges[(size_t)(N_NODES + 1) * CAP];

__device__ __forceinline__ float ldval(const float* p) { return __ldg(p); }
__device__ __forceinline__ float ldval(const __half* p) { return __half2float(__ldg(p)); }

// ---------------------------------------------------------------------------
// Layer-1 dense MM: s1[100000,12] = x @ W1, written as FP16 rows (stride 16).
// warp-per-row, float4 x loads, W1 staged in shared (pad 13).
// ---------------------------------------------------------------------------
__global__ void mm1_kernel(const float* __restrict__ x,
                           const float* __restrict__ W,
                           __half* __restrict__ out) {
    __shared__ float sW[512 * 13];
    for (int i = threadIdx.x; i < 512 * 12; i += blockDim.x) {
        int k = i / 12, j = i % 12;
        sW[k * 13 + j] = W[i];
    }
    __syncthreads();

    int warp = (blockIdx.x * blockDim.x + threadIdx.x) >> 5;
    int lane = threadIdx.x & 31;
    if (warp >= N_NODES) return;

    const float4* xr = reinterpret_cast<const float4*>(x + (size_t)warp * 512);
    float acc[12];
#pragma unroll
    for (int j = 0; j < 12; j++) acc[j] = 0.f;

#pragma unroll
    for (int it = 0; it < 4; it++) {
        int k4 = it * 32 + lane;
        float4 xv = xr[k4];
        int k = k4 * 4;
#pragma unroll
        for (int j = 0; j < 12; j++) {
            acc[j] = fmaf(xv.x, sW[(k + 0) * 13 + j], acc[j]);
            acc[j] = fmaf(xv.y, sW[(k + 1) * 13 + j], acc[j]);
            acc[j] = fmaf(xv.z, sW[(k + 2) * 13 + j], acc[j]);
            acc[j] = fmaf(xv.w, sW[(k + 3) * 13 + j], acc[j]);
        }
    }
#pragma unroll
    for (int j = 0; j < 12; j++) {
#pragma unroll
        for (int o = 16; o > 0; o >>= 1)
            acc[j] += __shfl_down_sync(0xffffffffu, acc[j], o);
    }
    if (lane == 0) {
        __half2* o = reinterpret_cast<__half2*>(out + (size_t)warp * 16);
#pragma unroll
        for (int j = 0; j < 6; j++)
            o[j] = __floats2half2_rn(acc[2 * j], acc[2 * j + 1]);
    }
}

// ---------------------------------------------------------------------------
// Bin edges by destination, 4 edges per thread (vector index loads).
// ---------------------------------------------------------------------------
__global__ void fill_bins_kernel(const float* __restrict__ ev,
                                 const int* __restrict__ src,
                                 const int* __restrict__ dst) {
    int t = blockIdx.x * blockDim.x + threadIdx.x;
    int e = t * 4;
    if (e + 4 <= N_EDGES) {
        float4 v4 = *reinterpret_cast<const float4*>(ev + e);
        int4 s4 = *reinterpret_cast<const int4*>(src + e);
        int4 d4 = *reinterpret_cast<const int4*>(dst + e);
        int p0 = atomicAdd(&g_cursor[d4.x], 1);
        int p1 = atomicAdd(&g_cursor[d4.y], 1);
        int p2 = atomicAdd(&g_cursor[d4.z], 1);
        int p3 = atomicAdd(&g_cursor[d4.w], 1);
        if (p0 < CAP) g_edges[(size_t)d4.x * CAP + p0] = make_float2(v4.x, __int_as_float(s4.x));
        if (p1 < CAP) g_edges[(size_t)d4.y * CAP + p1] = make_float2(v4.y, __int_as_float(s4.y));
        if (p2 < CAP) g_edges[(size_t)d4.z * CAP + p2] = make_float2(v4.z, __int_as_float(s4.z));
        if (p3 < CAP) g_edges[(size_t)d4.w * CAP + p3] = make_float2(v4.w, __int_as_float(s4.w));
    } else {
        for (; e < N_EDGES; e++) {
            int d = dst[e];
            int pos = atomicAdd(&g_cursor[d], 1);
            if (pos < CAP)
                g_edges[(size_t)d * CAP + pos] = make_float2(ev[e], __int_as_float(src[e]));
        }
    }
}

// ---------------------------------------------------------------------------
// STAGED gather (wide layers, SUB=16/NPW=2). Tin selects row precision
// (fp16 rows = 1 L2 sector/edge). OUTHALF selects fp16 output rows.
// ---------------------------------------------------------------------------
template <typename Tin, bool OUTHALF, int DIN, int SUB, int SIN, int DOUT, int SOUT,
          int ACT, bool BPRE, bool GEMM, bool BPOST>
__global__ void __launch_bounds__(256, 8)
gather_staged_kernel(const Tin* __restrict__ s,
                     const float* __restrict__ W,
                     const float* __restrict__ bpre,
                     const float* __restrict__ bpost,
                     void* __restrict__ outv) {
    constexpr int NPW = 32 / SUB;     // nodes per warp
    constexpr int N4 = CAP / 2;       // float4 slots per node (48)
    __shared__ float4 sel[8][NPW][N4 + 1];
    __shared__ float sW[GEMM ? DIN * DOUT : 1];
    __shared__ float sbpre[DIN];
    __shared__ float sbpost[BPOST ? DOUT : 1];
    __shared__ float sh[8][NPW][SUB];

    if (GEMM)
        for (int i = threadIdx.x; i < DIN * DOUT; i += blockDim.x) sW[i] = W[i];
    if (BPRE && threadIdx.x < DIN) sbpre[threadIdx.x] = bpre[threadIdx.x];
    if (BPOST && threadIdx.x < DOUT) sbpost[threadIdx.x] = bpost[threadIdx.x];
    __syncthreads();

    const int warpid = threadIdx.x >> 5;
    const int lane = threadIdx.x & 31;
    const int sub = lane / SUB;
    const int j = lane & (SUB - 1);
    const int node = ((blockIdx.x * blockDim.x + threadIdx.x) >> 5) * NPW + sub;
    const bool valid = node < N_NODES;

    int deg = 0;
    if (valid) {
        deg = g_cursor[node];
        deg = deg < CAP ? deg : CAP;
    }

    // stage packed edge list into smem (cached loads -> L2-resident for later passes)
    {
        const float4* el4 = reinterpret_cast<const float4*>(&g_edges[(size_t)node * CAP]);
        int n4 = (deg + 1) >> 1;
        for (int c = j; c < n4; c += SUB)
            sel[warpid][sub][c] = __ldg(el4 + c);
    }
    __syncwarp();

    const unsigned joff = (j < DIN) ? (unsigned)j : 0u;
    const Tin* scol = s + joff;
    const float4* myel = sel[warpid][sub];

    float a0 = 0.f, a1 = 0.f, a2 = 0.f, a3 = 0.f;
    const int iters = deg >> 3;

    for (int it = 0; it < iters; it++) {
        float4 p0 = myel[4 * it + 0];
        float4 p1 = myel[4 * it + 1];
        float4 p2 = myel[4 * it + 2];
        float4 p3 = myel[4 * it + 3];
        float r0 = ldval(scol + (unsigned)__float_as_int(p0.y) * SIN);
        float r1 = ldval(scol + (unsigned)__float_as_int(p0.w) * SIN);
        float r2 = ldval(scol + (unsigned)__float_as_int(p1.y) * SIN);
        float r3 = ldval(scol + (unsigned)__float_as_int(p1.w) * SIN);
        float r4 = ldval(scol + (unsigned)__float_as_int(p2.y) * SIN);
        float r5 = ldval(scol + (unsigned)__float_as_int(p2.w) * SIN);
        float r6 = ldval(scol + (unsigned)__float_as_int(p3.y) * SIN);
        float r7 = ldval(scol + (unsigned)__float_as_int(p3.w) * SIN);
        a0 = fmaf(p0.x, r0, a0);
        a1 = fmaf(p0.z, r1, a1);
        a2 = fmaf(p1.x, r2, a2);
        a3 = fmaf(p1.z, r3, a3);
        a0 = fmaf(p2.x, r4, a0);
        a1 = fmaf(p2.z, r5, a1);
        a2 = fmaf(p3.x, r6, a2);
        a3 = fmaf(p3.z, r7, a3);
    }
    {
        const float2* selt = reinterpret_cast<const float2*>(myel);
        for (int e = iters << 3; e < deg; e++) {
            float2 ed = selt[e];
            a0 = fmaf(ed.x, ldval(scol + (unsigned)__float_as_int(ed.y) * SIN), a0);
        }
    }
    float acc = (a0 + a1) + (a2 + a3);

    float h = acc;
    if (j < DIN) {
        if (BPRE) h += sbpre[j];
        if (ACT == 1) h = fmaxf(h, 0.f);
        else if (ACT == 2) h = h - tanhf(h);
    } else {
        h = 0.f;
    }

    if (!GEMM) {
        if (valid && j < DIN) {
            if (OUTHALF) reinterpret_cast<__half*>(outv)[(size_t)node * SOUT + j] = __float2half(h);
            else         reinterpret_cast<float*>(outv)[(size_t)node * SOUT + j] = h;
        }
        return;
    }

    sh[warpid][sub][j] = h;
    __syncwarp();

    if (valid) {
#pragma unroll
        for (int jo = j; jo < DOUT; jo += SUB) {
            float a = BPOST ? sbpost[jo] : 0.f;
#pragma unroll
            for (int k = 0; k < DIN; k++)
                a = fmaf(sh[warpid][sub][k], sW[k * DOUT + jo], a);
            if (OUTHALF) reinterpret_cast<__half*>(outv)[(size_t)node * SOUT + jo] = __float2half(a);
            else         reinterpret_cast<float*>(outv)[(size_t)node * SOUT + jo] = a;
        }
    }
}

// ---------------------------------------------------------------------------
// REGISTER-PIPELINED gather (narrow layers, fp32): unroll-4 with elist
// prefetch. [R14 winner verbatim]
// ---------------------------------------------------------------------------
template <int DIN, int SUB, int SIN, int DOUT, int SOUT,
          int ACT, bool BPRE, bool GEMM, bool BPOST>
__global__ void __launch_bounds__(256, 6)
gather_reg_kernel(const float* __restrict__ s,
                  const float* __restrict__ W,
                  const float* __restrict__ bpre,
                  const float* __restrict__ bpost,
                  float* __restrict__ out) {
    constexpr int NPW = 32 / SUB;
    __shared__ float sW[GEMM ? DIN * DOUT : 1];
    __shared__ float sbpre[DIN];
    __shared__ float sbpost[BPOST ? DOUT : 1];
    __shared__ float sh[8][NPW][SUB];

    if (GEMM)
        for (int i = threadIdx.x; i < DIN * DOUT; i += blockDim.x) sW[i] = W[i];
    if (BPRE && threadIdx.x < DIN) sbpre[threadIdx.x] = bpre[threadIdx.x];
    if (BPOST && threadIdx.x < DOUT) sbpost[threadIdx.x] = bpost[threadIdx.x];
    __syncthreads();

    const int warpid = threadIdx.x >> 5;
    const int lane = threadIdx.x & 31;
    const int sub = lane / SUB;
    const int j = lane & (SUB - 1);
    const int node = ((blockIdx.x * blockDim.x + threadIdx.x) >> 5) * NPW + sub;
    const bool valid = node < N_NODES;

    int deg = 0;
    if (valid) {
        deg = g_cursor[node];
        deg = deg < CAP ? deg : CAP;
    }

    const float4* el4 = reinterpret_cast<const float4*>(&g_edges[(size_t)node * CAP]);
    const unsigned joff = (j < DIN) ? (unsigned)j : 0u;
    const float* scol = s + joff;

    float a0 = 0.f, a1 = 0.f, a2 = 0.f, a3 = 0.f;
    const int iters = deg >> 2;

    float4 q0, q1;
    if (iters > 0) { q0 = __ldg(el4 + 0); q1 = __ldg(el4 + 1); }
    for (int it = 0; it < iters; it++) {
        float4 p0 = q0, p1 = q1;
        q0 = __ldg(el4 + 2 * it + 2);
        q1 = __ldg(el4 + 2 * it + 3);
        float r0 = __ldg(scol + (unsigned)__float_as_int(p0.y) * SIN);
        float r1 = __ldg(scol + (unsigned)__float_as_int(p0.w) * SIN);
        float r2 = __ldg(scol + (unsigned)__float_as_int(p1.y) * SIN);
        float r3 = __ldg(scol + (unsigned)__float_as_int(p1.w) * SIN);
        a0 = fmaf(p0.x, r0, a0);
        a1 = fmaf(p0.z, r1, a1);
        a2 = fmaf(p1.x, r2, a2);
        a3 = fmaf(p1.z, r3, a3);
    }
    for (int e = iters << 2; e < deg; e++) {
        float2 ed = g_edges[(size_t)node * CAP + e];
        a0 = fmaf(ed.x, __ldg(scol + (unsigned)__float_as_int(ed.y) * SIN), a0);
    }
    float acc = (a0 + a1) + (a2 + a3);

    float h = acc;
    if (j < DIN) {
        if (BPRE) h += sbpre[j];
        if (ACT == 1) h = fmaxf(h, 0.f);
        else if (ACT == 2) h = h - tanhf(h);
    } else {
        h = 0.f;
    }

    if (!GEMM) {
        if (valid && j < DIN) out[(size_t)node * SOUT + j] = h;
        return;
    }

    sh[warpid][sub][j] = h;
    __syncwarp();

    if (valid) {
#pragma unroll
        for (int jo = j; jo < DOUT; jo += SUB) {
            float a = BPOST ? sbpost[jo] : 0.f;
#pragma unroll
            for (int k = 0; k < DIN; k++)
                a = fmaf(sh[warpid][sub][k], sW[k * DOUT + jo], a);
            out[(size_t)node * SOUT + jo] = a;
        }
    }
}

// ---------------------------------------------------------------------------
// Launch. fill_bins on a side stream, fork-join overlapped with mm1.
// ---------------------------------------------------------------------------
extern "C" void kernel_launch(void* const* d_in, const int* in_sizes, int n_in,
                              void* d_out, int out_size) {
    const float* x = nullptr;
    const float* ev = nullptr;
    const int* esrc = nullptr;
    const int* edst = nullptr;
    const float* W[6] = {0};
    const float* b[6] = {0};
    const int wsz[6] = {512 * 12, 12 * 10, 10 * 8, 8 * 6, 6 * 4, 4 * 7};
    const int bsz[6] = {12, 10, 8, 6, 4, 7};

    int edgeSeen = 0;
    for (int i = 0; i < n_in; i++) {
        int sz = in_sizes[i];
        if (sz == N_NODES * 512) {
            x = (const float*)d_in[i];
        } else if (sz == N_EDGES) {
            if (edgeSeen == 0) ev = (const float*)d_in[i];
            else if (edgeSeen == 1) esrc = (const int*)d_in[i];
            else edst = (const int*)d_in[i];
            edgeSeen++;
        } else {
            for (int j = 0; j < 6; j++) {
                if (sz == wsz[j]) W[j] = (const float*)d_in[i];
                else if (sz == bsz[j]) b[j] = (const float*)d_in[i];
            }
        }
    }

    float* bufA = nullptr;
    float* bufB = nullptr;
    int* cursor = nullptr;
    cudaGetSymbolAddress((void**)&bufA, g_bufA);
    cudaGetSymbolAddress((void**)&bufB, g_bufB);
    cudaGetSymbolAddress((void**)&cursor, g_cursor);
    float* out = (float*)d_out;

    __half* bufAh = reinterpret_cast<__half*>(bufA);
    __half* bufBh = reinterpret_cast<__half*>(bufB);

    const int TB = 256;
    auto blocks = [](long long n, int tb) { return (int)((n + tb - 1) / tb); };

    const int WB = blocks((long long)N_NODES * 32, TB);
    auto gridFor = [&](int NPW) {
        long long warps = (N_NODES + NPW - 1) / NPW;
        return blocks(warps * 32, TB);
    };

    // ---- fork: fill_bins (side stream) || mm1 (main stream) ----
    cudaStream_t side = 0;
    cudaEvent_t evFork = 0, evJoin = 0;
    bool forked = (cudaStreamCreateWithFlags(&side, cudaStreamNonBlocking) == cudaSuccess) &&
                  (cudaEventCreateWithFlags(&evFork, cudaEventDisableTiming) == cudaSuccess) &&
                  (cudaEventCreateWithFlags(&evJoin, cudaEventDisableTiming) == cudaSuccess);

    cudaMemsetAsync(cursor, 0, (size_t)N_NODES * sizeof(int));
    if (forked) {
        cudaEventRecord(evFork, cudaStreamPerThread);
        cudaStreamWaitEvent(side, evFork, 0);
        fill_bins_kernel<<<blocks((N_EDGES + 3) / 4, TB), TB, 0, side>>>(ev, esrc, edst);
        mm1_kernel<<<WB, TB>>>(x, W[0], bufAh);
        cudaEventRecord(evJoin, side);
        cudaStreamWaitEvent(cudaStreamPerThread, evJoin, 0);
    } else {
        fill_bins_kernel<<<blocks((N_EDGES + 3) / 4, TB), TB>>>(ev, esrc, edst);
        mm1_kernel<<<WB, TB>>>(x, W[0], bufAh);
    }

    // p1: h1 = agg(s1f16)+b1 ; s2 = h1@W2 (fp16) (DIN=12 SUB=16 SIN=16 -> 10w s16h)
    gather_staged_kernel<__half, true, 12, 16, 16, 10, 16, 0, true, true, false>
        <<<gridFor(2), TB>>>(bufAh, W[1], b[0], nullptr, bufBh);
    // p2: h2 = relu(agg(s2f16)+b2) ; s3 = h2@W3 (fp32) (DIN=10 SUB=16 SIN=16 -> 8w s8)
    gather_staged_kernel<__half, false, 10, 16, 16, 8, 8, 1, true, true, false>
        <<<gridFor(2), TB>>>(bufBh, W[2], b[1], nullptr, bufA);
    // p3: h3 = ts(agg(s3)+b3) ; s4 = h3@W4     (DIN=8 SUB=8 SIN=8 -> 6w s8)
    gather_reg_kernel<8, 8, 8, 6, 8, 2, true, true, false>
        <<<gridFor(4), TB>>>(bufA, W[3], b[2], nullptr, bufB);
    // p4: h4 = ts(agg(s4)+b4) ; s5 = h4@W5     (DIN=6 SUB=8 SIN=8 -> 4w s4)
    gather_reg_kernel<6, 8, 8, 4, 4, 2, true, true, false>
        <<<gridFor(4), TB>>>(bufB, W[4], b[3], nullptr, bufA);
    // p5: h5 = agg(s5)+b5                      (DIN=4 SUB=4 SIN=4 -> 4w s4, no GEMM)
    gather_reg_kernel<4, 4, 4, 4, 4, 0, true, false, false>
        <<<gridFor(8), TB>>>(bufA, nullptr, b[4], nullptr, bufB);
    // p6: out = (agg(h5))@W6 + b6              (DIN=4 SUB=4 SIN=4 -> 7w packed)
    gather_reg_kernel<4, 4, 4, 7, 7, 0, false, true, true>
        <<<gridFor(8), TB>>>(bufB, W[5], nullptr, b[5], out);

    if (forked) {
        cudaStreamDestroy(side);
        cudaEventDestroy(evFork);
        cudaEventDestroy(evJoin);
    }

    (void)out_size;
}

// round 16
// speedup vs baseline: 1.7882x; 1.1587x over previous
#include <cuda_runtime.h>
#include <cuda_fp16.h>
#include <math.h>

#define N_NODES 100000
#define N_EDGES 3200000
#define CAP 96          // max in-degree slots (Poisson(32): P(deg>96) ~ 1e-20)

// Scratch (static device globals; no allocation). Max stride 16 floats.
__device__ __align__(128) float g_bufA[(size_t)N_NODES * 16];
__device__ __align__(128) float g_bufB[(size_t)N_NODES * 16];
__device__ int    g_cursor[N_NODES];
// +1 node padding: register-pipelined prefetch may read past the last bin
__device__ __align__(128) float2 g_edges[(size_t)(N_NODES + 1) * CAP];

__device__ __forceinline__ float ldval(const float* p) { return __ldg(p); }
__device__ __forceinline__ float ldval(const __half* p) { return __half2float(__ldg(p)); }

// ---------------------------------------------------------------------------
// Layer-1 dense MM, M-BLOCKED: each warp computes TWO rows, reusing every
// smem W value for both rows (halves LDS traffic — the mm1 floor).
// s1 written as FP16 rows (stride 16 halves).
// ---------------------------------------------------------------------------
__global__ void __launch_bounds__(256, 5)
mm1_kernel(const float* __restrict__ x,
           const float* __restrict__ W,
           __half* __restrict__ out) {
    __shared__ float sW[512 * 13];
    for (int i = threadIdx.x; i < 512 * 12; i += blockDim.x) {
        int k = i / 12, j = i % 12;
        sW[k * 13 + j] = W[i];
    }
    __syncthreads();

    int warp = (blockIdx.x * blockDim.x + threadIdx.x) >> 5;
    int lane = threadIdx.x & 31;
    int r0 = warp * 2;
    if (r0 >= N_NODES) return;          // N_NODES even -> r0+1 also valid

    const float4* xr0 = reinterpret_cast<const float4*>(x + (size_t)r0 * 512);
    const float4* xr1 = reinterpret_cast<const float4*>(x + (size_t)(r0 + 1) * 512);

    float acc0[12], acc1[12];
#pragma unroll
    for (int j = 0; j < 12; j++) { acc0[j] = 0.f; acc1[j] = 0.f; }

#pragma unroll
    for (int it = 0; it < 4; it++) {
        int k4 = it * 32 + lane;
        float4 xv0 = xr0[k4];
        float4 xv1 = xr1[k4];
        int k = k4 * 4;
#pragma unroll
        for (int c = 0; c < 4; c++) {
            float xc0 = (c == 0) ? xv0.x : (c == 1) ? xv0.y : (c == 2) ? xv0.z : xv0.w;
            float xc1 = (c == 0) ? xv1.x : (c == 1) ? xv1.y : (c == 2) ? xv1.z : xv1.w;
            const float* wr = sW + (k + c) * 13;
#pragma unroll
            for (int j = 0; j < 12; j++) {
                float w = wr[j];                  // loaded once, used twice
                acc0[j] = fmaf(xc0, w, acc0[j]);
                acc1[j] = fmaf(xc1, w, acc1[j]);
            }
        }
    }
#pragma unroll
    for (int j = 0; j < 12; j++) {
#pragma unroll
        for (int o = 16; o > 0; o >>= 1) {
            acc0[j] += __shfl_down_sync(0xffffffffu, acc0[j], o);
            acc1[j] += __shfl_down_sync(0xffffffffu, acc1[j], o);
        }
    }
    if (lane == 0) {
        __half2* o0 = reinterpret_cast<__half2*>(out + (size_t)r0 * 16);
        __half2* o1 = reinterpret_cast<__half2*>(out + (size_t)(r0 + 1) * 16);
#pragma unroll
        for (int j = 0; j < 6; j++) {
            o0[j] = __floats2half2_rn(acc0[2 * j], acc0[2 * j + 1]);
            o1[j] = __floats2half2_rn(acc1[2 * j], acc1[2 * j + 1]);
        }
    }
}

// ---------------------------------------------------------------------------
// Bin edges by destination, 4 edges per thread (vector index loads).
// ---------------------------------------------------------------------------
__global__ void fill_bins_kernel(const float* __restrict__ ev,
                                 const int* __restrict__ src,
                                 const int* __restrict__ dst) {
    int t = blockIdx.x * blockDim.x + threadIdx.x;
    int e = t * 4;
    if (e + 4 <= N_EDGES) {
        float4 v4 = *reinterpret_cast<const float4*>(ev + e);
        int4 s4 = *reinterpret_cast<const int4*>(src + e);
        int4 d4 = *reinterpret_cast<const int4*>(dst + e);
        int p0 = atomicAdd(&g_cursor[d4.x], 1);
        int p1 = atomicAdd(&g_cursor[d4.y], 1);
        int p2 = atomicAdd(&g_cursor[d4.z], 1);
        int p3 = atomicAdd(&g_cursor[d4.w], 1);
        if (p0 < CAP) g_edges[(size_t)d4.x * CAP + p0] = make_float2(v4.x, __int_as_float(s4.x));
        if (p1 < CAP) g_edges[(size_t)d4.y * CAP + p1] = make_float2(v4.y, __int_as_float(s4.y));
        if (p2 < CAP) g_edges[(size_t)d4.z * CAP + p2] = make_float2(v4.z, __int_as_float(s4.z));
        if (p3 < CAP) g_edges[(size_t)d4.w * CAP + p3] = make_float2(v4.w, __int_as_float(s4.w));
    } else {
        for (; e < N_EDGES; e++) {
            int d = dst[e];
            int pos = atomicAdd(&g_cursor[d], 1);
            if (pos < CAP)
                g_edges[(size_t)d * CAP + pos] = make_float2(ev[e], __int_as_float(src[e]));
        }
    }
}

// ---------------------------------------------------------------------------
// STAGED gather (wide layers, SUB=16/NPW=2). Tin selects row precision.
// ---------------------------------------------------------------------------
template <typename Tin, bool OUTHALF, int DIN, int SUB, int SIN, int DOUT, int SOUT,
          int ACT, bool BPRE, bool GEMM, bool BPOST>
__global__ void __launch_bounds__(256, 8)
gather_staged_kernel(const Tin* __restrict__ s,
                     const float* __restrict__ W,
                     const float* __restrict__ bpre,
                     const float* __restrict__ bpost,
                     void* __restrict__ outv) {
    constexpr int NPW = 32 / SUB;     // nodes per warp
    constexpr int N4 = CAP / 2;       // float4 slots per node (48)
    __shared__ float4 sel[8][NPW][N4 + 1];
    __shared__ float sW[GEMM ? DIN * DOUT : 1];
    __shared__ float sbpre[DIN];
    __shared__ float sbpost[BPOST ? DOUT : 1];
    __shared__ float sh[8][NPW][SUB];

    if (GEMM)
        for (int i = threadIdx.x; i < DIN * DOUT; i += blockDim.x) sW[i] = W[i];
    if (BPRE && threadIdx.x < DIN) sbpre[threadIdx.x] = bpre[threadIdx.x];
    if (BPOST && threadIdx.x < DOUT) sbpost[threadIdx.x] = bpost[threadIdx.x];
    __syncthreads();

    const int warpid = threadIdx.x >> 5;
    const int lane = threadIdx.x & 31;
    const int sub = lane / SUB;
    const int j = lane & (SUB - 1);
    const int node = ((blockIdx.x * blockDim.x + threadIdx.x) >> 5) * NPW + sub;
    const bool valid = node < N_NODES;

    int deg = 0;
    if (valid) {
        deg = g_cursor[node];
        deg = deg < CAP ? deg : CAP;
    }

    {
        const float4* el4 = reinterpret_cast<const float4*>(&g_edges[(size_t)node * CAP]);
        int n4 = (deg + 1) >> 1;
        for (int c = j; c < n4; c += SUB)
            sel[warpid][sub][c] = __ldg(el4 + c);
    }
    __syncwarp();

    const unsigned joff = (j < DIN) ? (unsigned)j : 0u;
    const Tin* scol = s + joff;
    const float4* myel = sel[warpid][sub];

    float a0 = 0.f, a1 = 0.f, a2 = 0.f, a3 = 0.f;
    const int iters = deg >> 3;

    for (int it = 0; it < iters; it++) {
        float4 p0 = myel[4 * it + 0];
        float4 p1 = myel[4 * it + 1];
        float4 p2 = myel[4 * it + 2];
        float4 p3 = myel[4 * it + 3];
        float r0 = ldval(scol + (unsigned)__float_as_int(p0.y) * SIN);
        float r1 = ldval(scol + (unsigned)__float_as_int(p0.w) * SIN);
        float r2 = ldval(scol + (unsigned)__float_as_int(p1.y) * SIN);
        float r3 = ldval(scol + (unsigned)__float_as_int(p1.w) * SIN);
        float r4 = ldval(scol + (unsigned)__float_as_int(p2.y) * SIN);
        float r5 = ldval(scol + (unsigned)__float_as_int(p2.w) * SIN);
        float r6 = ldval(scol + (unsigned)__float_as_int(p3.y) * SIN);
        float r7 = ldval(scol + (unsigned)__float_as_int(p3.w) * SIN);
        a0 = fmaf(p0.x, r0, a0);
        a1 = fmaf(p0.z, r1, a1);
        a2 = fmaf(p1.x, r2, a2);
        a3 = fmaf(p1.z, r3, a3);
        a0 = fmaf(p2.x, r4, a0);
        a1 = fmaf(p2.z, r5, a1);
        a2 = fmaf(p3.x, r6, a2);
        a3 = fmaf(p3.z, r7, a3);
    }
    {
        const float2* selt = reinterpret_cast<const float2*>(myel);
        for (int e = iters << 3; e < deg; e++) {
            float2 ed = selt[e];
            a0 = fmaf(ed.x, ldval(scol + (unsigned)__float_as_int(ed.y) * SIN), a0);
        }
    }
    float acc = (a0 + a1) + (a2 + a3);

    float h = acc;
    if (j < DIN) {
        if (BPRE) h += sbpre[j];
        if (ACT == 1) h = fmaxf(h, 0.f);
        else if (ACT == 2) h = h - tanhf(h);
    } else {
        h = 0.f;
    }

    if (!GEMM) {
        if (valid && j < DIN) {
            if (OUTHALF) reinterpret_cast<__half*>(outv)[(size_t)node * SOUT + j] = __float2half(h);
            else         reinterpret_cast<float*>(outv)[(size_t)node * SOUT + j] = h;
        }
        return;
    }

    sh[warpid][sub][j] = h;
    __syncwarp();

    if (valid) {
#pragma unroll
        for (int jo = j; jo < DOUT; jo += SUB) {
            float a = BPOST ? sbpost[jo] : 0.f;
#pragma unroll
            for (int k = 0; k < DIN; k++)
                a = fmaf(sh[warpid][sub][k], sW[k * DOUT + jo], a);
            if (OUTHALF) reinterpret_cast<__half*>(outv)[(size_t)node * SOUT + jo] = __float2half(a);
            else         reinterpret_cast<float*>(outv)[(size_t)node * SOUT + jo] = a;
        }
    }
}

// ---------------------------------------------------------------------------
// REGISTER-PIPELINED gather (narrow layers, fp32): unroll-4 with elist
// prefetch. [R14/R15 winner verbatim]
// ---------------------------------------------------------------------------
template <int DIN, int SUB, int SIN, int DOUT, int SOUT,
          int ACT, bool BPRE, bool GEMM, bool BPOST>
__global__ void __launch_bounds__(256, 6)
gather_reg_kernel(const float* __restrict__ s,
                  const float* __restrict__ W,
                  const float* __restrict__ bpre,
                  const float* __restrict__ bpost,
                  float* __restrict__ out) {
    constexpr int NPW = 32 / SUB;
    __shared__ float sW[GEMM ? DIN * DOUT : 1];
    __shared__ float sbpre[DIN];
    __shared__ float sbpost[BPOST ? DOUT : 1];
    __shared__ float sh[8][NPW][SUB];

    if (GEMM)
        for (int i = threadIdx.x; i < DIN * DOUT; i += blockDim.x) sW[i] = W[i];
    if (BPRE && threadIdx.x < DIN) sbpre[threadIdx.x] = bpre[threadIdx.x];
    if (BPOST && threadIdx.x < DOUT) sbpost[threadIdx.x] = bpost[threadIdx.x];
    __syncthreads();

    const int warpid = threadIdx.x >> 5;
    const int lane = threadIdx.x & 31;
    const int sub = lane / SUB;
    const int j = lane & (SUB - 1);
    const int node = ((blockIdx.x * blockDim.x + threadIdx.x) >> 5) * NPW + sub;
    const bool valid = node < N_NODES;

    int deg = 0;
    if (valid) {
        deg = g_cursor[node];
        deg = deg < CAP ? deg : CAP;
    }

    const float4* el4 = reinterpret_cast<const float4*>(&g_edges[(size_t)node * CAP]);
    const unsigned joff = (j < DIN) ? (unsigned)j : 0u;
    const float* scol = s + joff;

    float a0 = 0.f, a1 = 0.f, a2 = 0.f, a3 = 0.f;
    const int iters = deg >> 2;

    float4 q0, q1;
    if (iters > 0) { q0 = __ldg(el4 + 0); q1 = __ldg(el4 + 1); }
    for (int it = 0; it < iters; it++) {
        float4 p0 = q0, p1 = q1;
        q0 = __ldg(el4 + 2 * it + 2);
        q1 = __ldg(el4 + 2 * it + 3);
        float r0 = __ldg(scol + (unsigned)__float_as_int(p0.y) * SIN);
        float r1 = __ldg(scol + (unsigned)__float_as_int(p0.w) * SIN);
        float r2 = __ldg(scol + (unsigned)__float_as_int(p1.y) * SIN);
        float r3 = __ldg(scol + (unsigned)__float_as_int(p1.w) * SIN);
        a0 = fmaf(p0.x, r0, a0);
        a1 = fmaf(p0.z, r1, a1);
        a2 = fmaf(p1.x, r2, a2);
        a3 = fmaf(p1.z, r3, a3);
    }
    for (int e = iters << 2; e < deg; e++) {
        float2 ed = g_edges[(size_t)node * CAP + e];
        a0 = fmaf(ed.x, __ldg(scol + (unsigned)__float_as_int(ed.y) * SIN), a0);
    }
    float acc = (a0 + a1) + (a2 + a3);

    float h = acc;
    if (j < DIN) {
        if (BPRE) h += sbpre[j];
        if (ACT == 1) h = fmaxf(h, 0.f);
        else if (ACT == 2) h = h - tanhf(h);
    } else {
        h = 0.f;
    }

    if (!GEMM) {
        if (valid && j < DIN) out[(size_t)node * SOUT + j] = h;
        return;
    }

    sh[warpid][sub][j] = h;
    __syncwarp();

    if (valid) {
#pragma unroll
        for (int jo = j; jo < DOUT; jo += SUB) {
            float a = BPOST ? sbpost[jo] : 0.f;
#pragma unroll
            for (int k = 0; k < DIN; k++)
                a = fmaf(sh[warpid][sub][k], sW[k * DOUT + jo], a);
            out[(size_t)node * SOUT + jo] = a;
        }
    }
}

// ---------------------------------------------------------------------------
// Launch. fill_bins on a side stream, fork-join overlapped with mm1.
// ---------------------------------------------------------------------------
extern "C" void kernel_launch(void* const* d_in, const int* in_sizes, int n_in,
                              void* d_out, int out_size) {
    const float* x = nullptr;
    const float* ev = nullptr;
    const int* esrc = nullptr;
    const int* edst = nullptr;
    const float* W[6] = {0};
    const float* b[6] = {0};
    const int wsz[6] = {512 * 12, 12 * 10, 10 * 8, 8 * 6, 6 * 4, 4 * 7};
    const int bsz[6] = {12, 10, 8, 6, 4, 7};

    int edgeSeen = 0;
    for (int i = 0; i < n_in; i++) {
        int sz = in_sizes[i];
        if (sz == N_NODES * 512) {
            x = (const float*)d_in[i];
        } else if (sz == N_EDGES) {
            if (edgeSeen == 0) ev = (const float*)d_in[i];
            else if (edgeSeen == 1) esrc = (const int*)d_in[i];
            else edst = (const int*)d_in[i];
            edgeSeen++;
        } else {
            for (int j = 0; j < 6; j++) {
                if (sz == wsz[j]) W[j] = (const float*)d_in[i];
                else if (sz == bsz[j]) b[j] = (const float*)d_in[i];
            }
        }
    }

    float* bufA = nullptr;
    float* bufB = nullptr;
    int* cursor = nullptr;
    cudaGetSymbolAddress((void**)&bufA, g_bufA);
    cudaGetSymbolAddress((void**)&bufB, g_bufB);
    cudaGetSymbolAddress((void**)&cursor, g_cursor);
    float* out = (float*)d_out;

    __half* bufAh = reinterpret_cast<__half*>(bufA);
    __half* bufBh = reinterpret_cast<__half*>(bufB);

    const int TB = 256;
    auto blocks = [](long long n, int tb) { return (int)((n + tb - 1) / tb); };

    // mm1: warp per 2 rows
    const int WB2 = blocks((long long)(N_NODES / 2) * 32, TB);
    auto gridFor = [&](int NPW) {
        long long warps = (N_NODES + NPW - 1) / NPW;
        return blocks(warps * 32, TB);
    };

    // ---- fork: fill_bins (side stream) || mm1 (main stream) ----
    cudaStream_t side = 0;
    cudaEvent_t evFork = 0, evJoin = 0;
    bool forked = (cudaStreamCreateWithFlags(&side, cudaStreamNonBlocking) == cudaSuccess) &&
                  (cudaEventCreateWithFlags(&evFork, cudaEventDisableTiming) == cudaSuccess) &&
                  (cudaEventCreateWithFlags(&evJoin, cudaEventDisableTiming) == cudaSuccess);

    cudaMemsetAsync(cursor, 0, (size_t)N_NODES * sizeof(int));
    if (forked) {
        cudaEventRecord(evFork, cudaStreamPerThread);
        cudaStreamWaitEvent(side, evFork, 0);
        fill_bins_kernel<<<blocks((N_EDGES + 3) / 4, TB), TB, 0, side>>>(ev, esrc, edst);
        mm1_kernel<<<WB2, TB>>>(x, W[0], bufAh);
        cudaEventRecord(evJoin, side);
        cudaStreamWaitEvent(cudaStreamPerThread, evJoin, 0);
    } else {
        fill_bins_kernel<<<blocks((N_EDGES + 3) / 4, TB), TB>>>(ev, esrc, edst);
        mm1_kernel<<<WB2, TB>>>(x, W[0], bufAh);
    }

    // p1: h1 = agg(s1f16)+b1 ; s2 = h1@W2 (fp16) (DIN=12 SUB=16 SIN=16 -> 10w s16h)
    gather_staged_kernel<__half, true, 12, 16, 16, 10, 16, 0, true, true, false>
        <<<gridFor(2), TB>>>(bufAh, W[1], b[0], nullptr, bufBh);
    // p2: h2 = relu(agg(s2f16)+b2) ; s3 = h2@W3 (fp32) (DIN=10 SUB=16 SIN=16 -> 8w s8)
    gather_staged_kernel<__half, false, 10, 16, 16, 8, 8, 1, true, true, false>
        <<<gridFor(2), TB>>>(bufBh, W[2], b[1], nullptr, bufA);
    // p3: h3 = ts(agg(s3)+b3) ; s4 = h3@W4     (DIN=8 SUB=8 SIN=8 -> 6w s8)
    gather_reg_kernel<8, 8, 8, 6, 8, 2, true, true, false>
        <<<gridFor(4), TB>>>(bufA, W[3], b[2], nullptr, bufB);
    // p4: h4 = ts(agg(s4)+b4) ; s5 = h4@W5     (DIN=6 SUB=8 SIN=8 -> 4w s4)
    gather_reg_kernel<6, 8, 8, 4, 4, 2, true, true, false>
        <<<gridFor(4), TB>>>(bufB, W[4], b[3], nullptr, bufA);
    // p5: h5 = agg(s5)+b5                      (DIN=4 SUB=4 SIN=4 -> 4w s4, no GEMM)
    gather_reg_kernel<4, 4, 4, 4, 4, 0, true, false, false>
        <<<gridFor(8), TB>>>(bufA, nullptr, b[4], nullptr, bufB);
    // p6: out = (agg(h5))@W6 + b6              (DIN=4 SUB=4 SIN=4 -> 7w packed)
    gather_reg_kernel<4, 4, 4, 7, 7, 0, false, true, true>
        <<<gridFor(8), TB>>>(bufB, W[5], nullptr, b[5], out);

    if (forked) {
        cudaStreamDestroy(side);
        cudaEventDestroy(evFork);
        cudaEventDestroy(evJoin);
    }

    (void)out_size;
}

// round 17
// speedup vs baseline: 1.8567x; 1.0383x over previous
#include <cuda_runtime.h>
#include <cuda_fp16.h>
#include <math.h>

#define N_NODES 100000
#define N_EDGES 3200000
#define CAP 96          // max in-degree slots (Poisson(32): P(deg>96) ~ 1e-20)

// Scratch (static device globals; no allocation). Max stride 16 floats.
__device__ __align__(128) float g_bufA[(size_t)N_NODES * 16];
__device__ __align__(128) float g_bufB[(size_t)N_NODES * 16];
__device__ int    g_cursor[N_NODES];
// +1 node padding: register-pipelined prefetch may read past the last bin
__device__ __align__(128) float2 g_edges[(size_t)(N_NODES + 1) * CAP];

__device__ __forceinline__ float ldval(const float* p) { return __ldg(p); }
__device__ __forceinline__ float ldval(const __half* p) { return __half2float(__ldg(p)); }

// ---------------------------------------------------------------------------
// Layer-1 dense MM, 4-ROW BLOCKED: each warp computes FOUR rows, reusing
// every smem W value 4x (quarters LDS warp-instructions vs 1-row).
// s1 written as FP16 rows (stride 16 halves).
// ---------------------------------------------------------------------------
__global__ void __launch_bounds__(256, 3)
mm1_kernel(const float* __restrict__ x,
           const float* __restrict__ W,
           __half* __restrict__ out) {
    __shared__ float sW[512 * 13];
    for (int i = threadIdx.x; i < 512 * 12; i += blockDim.x) {
        int k = i / 12, j = i % 12;
        sW[k * 13 + j] = W[i];
    }
    __syncthreads();

    int warp = (blockIdx.x * blockDim.x + threadIdx.x) >> 5;
    int lane = threadIdx.x & 31;
    int r0 = warp * 4;
    if (r0 >= N_NODES) return;          // N_NODES % 4 == 0 -> r0..r0+3 valid

    const float4* xr0 = reinterpret_cast<const float4*>(x + (size_t)(r0 + 0) * 512);
    const float4* xr1 = reinterpret_cast<const float4*>(x + (size_t)(r0 + 1) * 512);
    const float4* xr2 = reinterpret_cast<const float4*>(x + (size_t)(r0 + 2) * 512);
    const float4* xr3 = reinterpret_cast<const float4*>(x + (size_t)(r0 + 3) * 512);

    float acc0[12], acc1[12], acc2[12], acc3[12];
#pragma unroll
    for (int j = 0; j < 12; j++) { acc0[j] = 0.f; acc1[j] = 0.f; acc2[j] = 0.f; acc3[j] = 0.f; }

#pragma unroll
    for (int it = 0; it < 4; it++) {
        int k4 = it * 32 + lane;
        float4 xv0 = xr0[k4];
        float4 xv1 = xr1[k4];
        float4 xv2 = xr2[k4];
        float4 xv3 = xr3[k4];
        int k = k4 * 4;
#pragma unroll
        for (int c = 0; c < 4; c++) {
            float xc0 = (c == 0) ? xv0.x : (c == 1) ? xv0.y : (c == 2) ? xv0.z : xv0.w;
            float xc1 = (c == 0) ? xv1.x : (c == 1) ? xv1.y : (c == 2) ? xv1.z : xv1.w;
            float xc2 = (c == 0) ? xv2.x : (c == 1) ? xv2.y : (c == 2) ? xv2.z : xv2.w;
            float xc3 = (c == 0) ? xv3.x : (c == 1) ? xv3.y : (c == 2) ? xv3.z : xv3.w;
            const float* wr = sW + (k + c) * 13;
#pragma unroll
            for (int j = 0; j < 12; j++) {
                float w = wr[j];                  // loaded once, used 4x
                acc0[j] = fmaf(xc0, w, acc0[j]);
                acc1[j] = fmaf(xc1, w, acc1[j]);
                acc2[j] = fmaf(xc2, w, acc2[j]);
                acc3[j] = fmaf(xc3, w, acc3[j]);
            }
        }
    }
#pragma unroll
    for (int j = 0; j < 12; j++) {
#pragma unroll
        for (int o = 16; o > 0; o >>= 1) {
            acc0[j] += __shfl_down_sync(0xffffffffu, acc0[j], o);
            acc1[j] += __shfl_down_sync(0xffffffffu, acc1[j], o);
            acc2[j] += __shfl_down_sync(0xffffffffu, acc2[j], o);
            acc3[j] += __shfl_down_sync(0xffffffffu, acc3[j], o);
        }
    }
    if (lane == 0) {
        __half2* o0 = reinterpret_cast<__half2*>(out + (size_t)(r0 + 0) * 16);
        __half2* o1 = reinterpret_cast<__half2*>(out + (size_t)(r0 + 1) * 16);
        __half2* o2 = reinterpret_cast<__half2*>(out + (size_t)(r0 + 2) * 16);
        __half2* o3 = reinterpret_cast<__half2*>(out + (size_t)(r0 + 3) * 16);
#pragma unroll
        for (int j = 0; j < 6; j++) {
            o0[j] = __floats2half2_rn(acc0[2 * j], acc0[2 * j + 1]);
            o1[j] = __floats2half2_rn(acc1[2 * j], acc1[2 * j + 1]);
            o2[j] = __floats2half2_rn(acc2[2 * j], acc2[2 * j + 1]);
            o3[j] = __floats2half2_rn(acc3[2 * j], acc3[2 * j + 1]);
        }
    }
}

// ---------------------------------------------------------------------------
// Bin edges by destination, 4 edges per thread (vector index loads).
// ---------------------------------------------------------------------------
__global__ void fill_bins_kernel(const float* __restrict__ ev,
                                 const int* __restrict__ src,
                                 const int* __restrict__ dst) {
    int t = blockIdx.x * blockDim.x + threadIdx.x;
    int e = t * 4;
    if (e + 4 <= N_EDGES) {
        float4 v4 = *reinterpret_cast<const float4*>(ev + e);
        int4 s4 = *reinterpret_cast<const int4*>(src + e);
        int4 d4 = *reinterpret_cast<const int4*>(dst + e);
        int p0 = atomicAdd(&g_cursor[d4.x], 1);
        int p1 = atomicAdd(&g_cursor[d4.y], 1);
        int p2 = atomicAdd(&g_cursor[d4.z], 1);
        int p3 = atomicAdd(&g_cursor[d4.w], 1);
        if (p0 < CAP) g_edges[(size_t)d4.x * CAP + p0] = make_float2(v4.x, __int_as_float(s4.x));
        if (p1 < CAP) g_edges[(size_t)d4.y * CAP + p1] = make_float2(v4.y, __int_as_float(s4.y));
        if (p2 < CAP) g_edges[(size_t)d4.z * CAP + p2] = make_float2(v4.z, __int_as_float(s4.z));
        if (p3 < CAP) g_edges[(size_t)d4.w * CAP + p3] = make_float2(v4.w, __int_as_float(s4.w));
    } else {
        for (; e < N_EDGES; e++) {
            int d = dst[e];
            int pos = atomicAdd(&g_cursor[d], 1);
            if (pos < CAP)
                g_edges[(size_t)d * CAP + pos] = make_float2(ev[e], __int_as_float(src[e]));
        }
    }
}

// ---------------------------------------------------------------------------
// STAGED gather (wide layers, SUB=16/NPW=2). Tin selects row precision.
// ---------------------------------------------------------------------------
template <typename Tin, bool OUTHALF, int DIN, int SUB, int SIN, int DOUT, int SOUT,
          int ACT, bool BPRE, bool GEMM, bool BPOST>
__global__ void __launch_bounds__(256, 8)
gather_staged_kernel(const Tin* __restrict__ s,
                     const float* __restrict__ W,
                     const float* __restrict__ bpre,
                     const float* __restrict__ bpost,
                     void* __restrict__ outv) {
    constexpr int NPW = 32 / SUB;     // nodes per warp
    constexpr int N4 = CAP / 2;       // float4 slots per node (48)
    __shared__ float4 sel[8][NPW][N4 + 1];
    __shared__ float sW[GEMM ? DIN * DOUT : 1];
    __shared__ float sbpre[DIN];
    __shared__ float sbpost[BPOST ? DOUT : 1];
    __shared__ float sh[8][NPW][SUB];

    if (GEMM)
        for (int i = threadIdx.x; i < DIN * DOUT; i += blockDim.x) sW[i] = W[i];
    if (BPRE && threadIdx.x < DIN) sbpre[threadIdx.x] = bpre[threadIdx.x];
    if (BPOST && threadIdx.x < DOUT) sbpost[threadIdx.x] = bpost[threadIdx.x];
    __syncthreads();

    const int warpid = threadIdx.x >> 5;
    const int lane = threadIdx.x & 31;
    const int sub = lane / SUB;
    const int j = lane & (SUB - 1);
    const int node = ((blockIdx.x * blockDim.x + threadIdx.x) >> 5) * NPW + sub;
    const bool valid = node < N_NODES;

    int deg = 0;
    if (valid) {
        deg = g_cursor[node];
        deg = deg < CAP ? deg : CAP;
    }

    {
        const float4* el4 = reinterpret_cast<const float4*>(&g_edges[(size_t)node * CAP]);
        int n4 = (deg + 1) >> 1;
        for (int c = j; c < n4; c += SUB)
            sel[warpid][sub][c] = __ldg(el4 + c);
    }
    __syncwarp();

    const unsigned joff = (j < DIN) ? (unsigned)j : 0u;
    const Tin* scol = s + joff;
    const float4* myel = sel[warpid][sub];

    float a0 = 0.f, a1 = 0.f, a2 = 0.f, a3 = 0.f;
    const int iters = deg >> 3;

    for (int it = 0; it < iters; it++) {
        float4 p0 = myel[4 * it + 0];
        float4 p1 = myel[4 * it + 1];
        float4 p2 = myel[4 * it + 2];
        float4 p3 = myel[4 * it + 3];
        float r0 = ldval(scol + (unsigned)__float_as_int(p0.y) * SIN);
        float r1 = ldval(scol + (unsigned)__float_as_int(p0.w) * SIN);
        float r2 = ldval(scol + (unsigned)__float_as_int(p1.y) * SIN);
        float r3 = ldval(scol + (unsigned)__float_as_int(p1.w) * SIN);
        float r4 = ldval(scol + (unsigned)__float_as_int(p2.y) * SIN);
        float r5 = ldval(scol + (unsigned)__float_as_int(p2.w) * SIN);
        float r6 = ldval(scol + (unsigned)__float_as_int(p3.y) * SIN);
        float r7 = ldval(scol + (unsigned)__float_as_int(p3.w) * SIN);
        a0 = fmaf(p0.x, r0, a0);
        a1 = fmaf(p0.z, r1, a1);
        a2 = fmaf(p1.x, r2, a2);
        a3 = fmaf(p1.z, r3, a3);
        a0 = fmaf(p2.x, r4, a0);
        a1 = fmaf(p2.z, r5, a1);
        a2 = fmaf(p3.x, r6, a2);
        a3 = fmaf(p3.z, r7, a3);
    }
    {
        const float2* selt = reinterpret_cast<const float2*>(myel);
        for (int e = iters << 3; e < deg; e++) {
            float2 ed = selt[e];
            a0 = fmaf(ed.x, ldval(scol + (unsigned)__float_as_int(ed.y) * SIN), a0);
        }
    }
    float acc = (a0 + a1) + (a2 + a3);

    float h = acc;
    if (j < DIN) {
        if (BPRE) h += sbpre[j];
        if (ACT == 1) h = fmaxf(h, 0.f);
        else if (ACT == 2) h = h - tanhf(h);
    } else {
        h = 0.f;
    }

    if (!GEMM) {
        if (valid && j < DIN) {
            if (OUTHALF) reinterpret_cast<__half*>(outv)[(size_t)node * SOUT + j] = __float2half(h);
            else         reinterpret_cast<float*>(outv)[(size_t)node * SOUT + j] = h;
        }
        return;
    }

    sh[warpid][sub][j] = h;
    __syncwarp();

    if (valid) {
#pragma unroll
        for (int jo = j; jo < DOUT; jo += SUB) {
            float a = BPOST ? sbpost[jo] : 0.f;
#pragma unroll
            for (int k = 0; k < DIN; k++)
                a = fmaf(sh[warpid][sub][k], sW[k * DOUT + jo], a);
            if (OUTHALF) reinterpret_cast<__half*>(outv)[(size_t)node * SOUT + jo] = __float2half(a);
            else         reinterpret_cast<float*>(outv)[(size_t)node * SOUT + jo] = a;
        }
    }
}

// ---------------------------------------------------------------------------
// REGISTER-PIPELINED gather (narrow layers, fp32): unroll-4 with elist
// prefetch. [winner verbatim]
// ---------------------------------------------------------------------------
template <int DIN, int SUB, int SIN, int DOUT, int SOUT,
          int ACT, bool BPRE, bool GEMM, bool BPOST>
__global__ void __launch_bounds__(256, 6)
gather_reg_kernel(const float* __restrict__ s,
                  const float* __restrict__ W,
                  const float* __restrict__ bpre,
                  const float* __restrict__ bpost,
                  float* __restrict__ out) {
    constexpr int NPW = 32 / SUB;
    __shared__ float sW[GEMM ? DIN * DOUT : 1];
    __shared__ float sbpre[DIN];
    __shared__ float sbpost[BPOST ? DOUT : 1];
    __shared__ float sh[8][NPW][SUB];

    if (GEMM)
        for (int i = threadIdx.x; i < DIN * DOUT; i += blockDim.x) sW[i] = W[i];
    if (BPRE && threadIdx.x < DIN) sbpre[threadIdx.x] = bpre[threadIdx.x];
    if (BPOST && threadIdx.x < DOUT) sbpost[threadIdx.x] = bpost[threadIdx.x];
    __syncthreads();

    const int warpid = threadIdx.x >> 5;
    const int lane = threadIdx.x & 31;
    const int sub = lane / SUB;
    const int j = lane & (SUB - 1);
    const int node = ((blockIdx.x * blockDim.x + threadIdx.x) >> 5) * NPW + sub;
    const bool valid = node < N_NODES;

    int deg = 0;
    if (valid) {
        deg = g_cursor[node];
        deg = deg < CAP ? deg : CAP;
    }

    const float4* el4 = reinterpret_cast<const float4*>(&g_edges[(size_t)node * CAP]);
    const unsigned joff = (j < DIN) ? (unsigned)j : 0u;
    const float* scol = s + joff;

    float a0 = 0.f, a1 = 0.f, a2 = 0.f, a3 = 0.f;
    const int iters = deg >> 2;

    float4 q0, q1;
    if (iters > 0) { q0 = __ldg(el4 + 0); q1 = __ldg(el4 + 1); }
    for (int it = 0; it < iters; it++) {
        float4 p0 = q0, p1 = q1;
        q0 = __ldg(el4 + 2 * it + 2);
        q1 = __ldg(el4 + 2 * it + 3);
        float r0 = __ldg(scol + (unsigned)__float_as_int(p0.y) * SIN);
        float r1 = __ldg(scol + (unsigned)__float_as_int(p0.w) * SIN);
        float r2 = __ldg(scol + (unsigned)__float_as_int(p1.y) * SIN);
        float r3 = __ldg(scol + (unsigned)__float_as_int(p1.w) * SIN);
        a0 = fmaf(p0.x, r0, a0);
        a1 = fmaf(p0.z, r1, a1);
        a2 = fmaf(p1.x, r2, a2);
        a3 = fmaf(p1.z, r3, a3);
    }
    for (int e = iters << 2; e < deg; e++) {
        float2 ed = g_edges[(size_t)node * CAP + e];
        a0 = fmaf(ed.x, __ldg(scol + (unsigned)__float_as_int(ed.y) * SIN), a0);
    }
    float acc = (a0 + a1) + (a2 + a3);

    float h = acc;
    if (j < DIN) {
        if (BPRE) h += sbpre[j];
        if (ACT == 1) h = fmaxf(h, 0.f);
        else if (ACT == 2) h = h - tanhf(h);
    } else {
        h = 0.f;
    }

    if (!GEMM) {
        if (valid && j < DIN) out[(size_t)node * SOUT + j] = h;
        return;
    }

    sh[warpid][sub][j] = h;
    __syncwarp();

    if (valid) {
#pragma unroll
        for (int jo = j; jo < DOUT; jo += SUB) {
            float a = BPOST ? sbpost[jo] : 0.f;
#pragma unroll
            for (int k = 0; k < DIN; k++)
                a = fmaf(sh[warpid][sub][k], sW[k * DOUT + jo], a);
            out[(size_t)node * SOUT + jo] = a;
        }
    }
}

// ---------------------------------------------------------------------------
// Launch. fill_bins on a side stream, fork-join overlapped with mm1.
// ---------------------------------------------------------------------------
extern "C" void kernel_launch(void* const* d_in, const int* in_sizes, int n_in,
                              void* d_out, int out_size) {
    const float* x = nullptr;
    const float* ev = nullptr;
    const int* esrc = nullptr;
    const int* edst = nullptr;
    const float* W[6] = {0};
    const float* b[6] = {0};
    const int wsz[6] = {512 * 12, 12 * 10, 10 * 8, 8 * 6, 6 * 4, 4 * 7};
    const int bsz[6] = {12, 10, 8, 6, 4, 7};

    int edgeSeen = 0;
    for (int i = 0; i < n_in; i++) {
        int sz = in_sizes[i];
        if (sz == N_NODES * 512) {
            x = (const float*)d_in[i];
        } else if (sz == N_EDGES) {
            if (edgeSeen == 0) ev = (const float*)d_in[i];
            else if (edgeSeen == 1) esrc = (const int*)d_in[i];
            else edst = (const int*)d_in[i];
            edgeSeen++;
        } else {
            for (int j = 0; j < 6; j++) {
                if (sz == wsz[j]) W[j] = (const float*)d_in[i];
                else if (sz == bsz[j]) b[j] = (const float*)d_in[i];
            }
        }
    }

    float* bufA = nullptr;
    float* bufB = nullptr;
    int* cursor = nullptr;
    cudaGetSymbolAddress((void**)&bufA, g_bufA);
    cudaGetSymbolAddress((void**)&bufB, g_bufB);
    cudaGetSymbolAddress((void**)&cursor, g_cursor);
    float* out = (float*)d_out;

    __half* bufAh = reinterpret_cast<__half*>(bufA);
    __half* bufBh = reinterpret_cast<__half*>(bufB);

    const int TB = 256;
    auto blocks = [](long long n, int tb) { return (int)((n + tb - 1) / tb); };

    // mm1: warp per 4 rows
    const int WB4 = blocks((long long)(N_NODES / 4) * 32, TB);
    auto gridFor = [&](int NPW) {
        long long warps = (N_NODES + NPW - 1) / NPW;
        return blocks(warps * 32, TB);
    };

    // ---- fork: fill_bins (side stream) || mm1 (main stream) ----
    cudaStream_t side = 0;
    cudaEvent_t evFork = 0, evJoin = 0;
    bool forked = (cudaStreamCreateWithFlags(&side, cudaStreamNonBlocking) == cudaSuccess) &&
                  (cudaEventCreateWithFlags(&evFork, cudaEventDisableTiming) == cudaSuccess) &&
                  (cudaEventCreateWithFlags(&evJoin, cudaEventDisableTiming) == cudaSuccess);

    cudaMemsetAsync(cursor, 0, (size_t)N_NODES * sizeof(int));
    if (forked) {
        cudaEventRecord(evFork, cudaStreamPerThread);
        cudaStreamWaitEvent(side, evFork, 0);
        fill_bins_kernel<<<blocks((N_EDGES + 3) / 4, TB), TB, 0, side>>>(ev, esrc, edst);
        mm1_kernel<<<WB4, TB>>>(x, W[0], bufAh);
        cudaEventRecord(evJoin, side);
        cudaStreamWaitEvent(cudaStreamPerThread, evJoin, 0);
    } else {
        fill_bins_kernel<<<blocks((N_EDGES + 3) / 4, TB), TB>>>(ev, esrc, edst);
        mm1_kernel<<<WB4, TB>>>(x, W[0], bufAh);
    }

    // p1: h1 = agg(s1f16)+b1 ; s2 = h1@W2 (fp16) (DIN=12 SUB=16 SIN=16 -> 10w s16h)
    gather_staged_kernel<__half, true, 12, 16, 16, 10, 16, 0, true, true, false>
        <<<gridFor(2), TB>>>(bufAh, W[1], b[0], nullptr, bufBh);
    // p2: h2 = relu(agg(s2f16)+b2) ; s3 = h2@W3 (fp32) (DIN=10 SUB=16 SIN=16 -> 8w s8)
    gather_staged_kernel<__half, false, 10, 16, 16, 8, 8, 1, true, true, false>
        <<<gridFor(2), TB>>>(bufBh, W[2], b[1], nullptr, bufA);
    // p3: h3 = ts(agg(s3)+b3) ; s4 = h3@W4     (DIN=8 SUB=8 SIN=8 -> 6w s8)
    gather_reg_kernel<8, 8, 8, 6, 8, 2, true, true, false>
        <<<gridFor(4), TB>>>(bufA, W[3], b[2], nullptr, bufB);
    // p4: h4 = ts(agg(s4)+b4) ; s5 = h4@W5     (DIN=6 SUB=8 SIN=8 -> 4w s4)
    gather_reg_kernel<6, 8, 8, 4, 4, 2, true, true, false>
        <<<gridFor(4), TB>>>(bufB, W[4], b[3], nullptr, bufA);
    // p5: h5 = agg(s5)+b5                      (DIN=4 SUB=4 SIN=4 -> 4w s4, no GEMM)
    gather_reg_kernel<4, 4, 4, 4, 4, 0, true, false, false>
        <<<gridFor(8), TB>>>(bufA, nullptr, b[4], nullptr, bufB);
    // p6: out = (agg(h5))@W6 + b6              (DIN=4 SUB=4 SIN=4 -> 7w packed)
    gather_reg_kernel<4, 4, 4, 7, 7, 0, false, true, true>
        <<<gridFor(8), TB>>>(bufB, W[5], nullptr, b[5], out);

    if (forked) {
        cudaStreamDestroy(side);
        cudaEventDestroy(evFork);
        cudaEventDestroy(evJoin);
    }

    (void)out_size;
}